// round 14
// baseline (speedup 1.0000x reference)
#include <cuda_runtime.h>
#include <cuda_bf16.h>
#include <cstdint>

#define BB 4
#define CC 256
#define HH 128
#define WW 128
#define HWD (HH*WW)
#define NHEAD 8
#define DK 64
#define CO 512
#define KER 7
#define RAD 3
#define NN 49
#define LN_EPS 1e-6f

// attention tile
#define ATW 32
#define ATH 16
#define AHLW (ATW + 2*RAD)   // 38
#define AHLH (ATH + 2*RAD)   // 22
#define ANPOS (AHLW*AHLH)    // 836
#define NC4 (DK/4)

// HMMA GEMM tiles
#define BM 256
#define BN 64
#define BK 64
#define PITCHB 144           // bytes per 64-bf16 row: 9x16B -> conflict-free LDSM
// per-stage smem byte offsets
#define S_AHI 0
#define S_ALO (BM*PITCHB)                    // 36864
#define S_BHI (2*BM*PITCHB)                  // 73728
#define S_BLO (2*BM*PITCHB + BN*PITCHB)      // 82944
#define STAGE (2*BM*PITCHB + 2*BN*PITCHB)    // 92160
#define GEMM_SMEM (2*STAGE)                  // 184320

typedef unsigned long long u64;

// ---------------- scratch ----------------
__device__ float g_qh[33554432];
__device__ float g_kh[33554432];
__device__ float g_vh[33554432];
__device__ __nv_bfloat16 g_xhi[3][16777216];
__device__ __nv_bfloat16 g_xlo[3][16777216];
__device__ __nv_bfloat16 g_atthi[33554432];
__device__ __nv_bfloat16 g_attlo[33554432];
__device__ __nv_bfloat16 g_whi[524288];
__device__ __nv_bfloat16 g_wlo[524288];

// ---------------- PTX helpers ----------------
#define MMA_BF16(d0,d1,d2,d3, a0,a1,a2,a3, b0,b1) \
    asm volatile("mma.sync.aligned.m16n8k16.row.col.f32.bf16.bf16.f32 " \
        "{%0,%1,%2,%3}, {%4,%5,%6,%7}, {%8,%9}, {%0,%1,%2,%3};" \
        : "+f"(d0), "+f"(d1), "+f"(d2), "+f"(d3) \
        : "r"(a0), "r"(a1), "r"(a2), "r"(a3), "r"(b0), "r"(b1))

#define LDSM_X4(r0,r1,r2,r3, addr) \
    asm volatile("ldmatrix.sync.aligned.m8n8.x4.shared.b16 {%0,%1,%2,%3}, [%4];" \
        : "=r"(r0),"=r"(r1),"=r"(r2),"=r"(r3) : "r"(addr))

#define CP16(dst, src) \
    asm volatile("cp.async.cg.shared.global [%0], [%1], 16;" :: "r"(dst), "l"(src))
#define CP_COMMIT() asm volatile("cp.async.commit_group;")
#define CP_WAIT1()  asm volatile("cp.async.wait_group 1;")
#define CP_WAIT0()  asm volatile("cp.async.wait_group 0;")

// ---------------- element-wise fp32 -> bf16 hi/lo split (weights) ----------------
__global__ __launch_bounds__(256)
void split_kernel(const float* __restrict__ x, __nv_bfloat16* __restrict__ hi,
                  __nv_bfloat16* __restrict__ lo, int n)
{
    int i = (blockIdx.x * 256 + threadIdx.x) * 4;
    if (i >= n) return;
    float4 v = *(const float4*)(x + i);
    __nv_bfloat16 h0 = __float2bfloat16(v.x), h1 = __float2bfloat16(v.y);
    __nv_bfloat16 h2 = __float2bfloat16(v.z), h3 = __float2bfloat16(v.w);
    __nv_bfloat16 l0 = __float2bfloat16(v.x - __bfloat162float(h0));
    __nv_bfloat16 l1 = __float2bfloat16(v.y - __bfloat162float(h1));
    __nv_bfloat16 l2 = __float2bfloat16(v.z - __bfloat162float(h2));
    __nv_bfloat16 l3 = __float2bfloat16(v.w - __bfloat162float(h3));
    __nv_bfloat162* H = (__nv_bfloat162*)(hi + i);
    __nv_bfloat162* L = (__nv_bfloat162*)(lo + i);
    H[0] = __halves2bfloat162(h0, h1); H[1] = __halves2bfloat162(h2, h3);
    L[0] = __halves2bfloat162(l0, l1); L[1] = __halves2bfloat162(l2, l3);
}

// ---------------- transpose + split: X[b][c][p] -> X^T[b][p][c] bf16 hi/lo ----------------
__global__ __launch_bounds__(256)
void tsplit_kernel(const float* __restrict__ x, __nv_bfloat16* __restrict__ hi,
                   __nv_bfloat16* __restrict__ lo)
{
    __shared__ float t[32][33];
    int b = blockIdx.z, c0 = blockIdx.y * 32, p0 = blockIdx.x * 32;
    int tx = threadIdx.x & 31, ty = threadIdx.x >> 5;
    const float* src = x + ((size_t)b * CC + c0) * HWD + p0;
#pragma unroll
    for (int j = 0; j < 4; j++)
        t[ty + 8*j][tx] = src[(size_t)(ty + 8*j) * HWD + tx];
    __syncthreads();
#pragma unroll
    for (int j = 0; j < 4; j++) {
        float v = t[tx][ty + 8*j];
        size_t o = ((size_t)b * HWD + p0 + ty + 8*j) * CC + c0 + tx;
        __nv_bfloat16 hv = __float2bfloat16(v);
        hi[o] = hv;
        lo[o] = __float2bfloat16(v - __bfloat162float(hv));
    }
}

// ---------------- staging: one K-chunk into stage buffer via cp.async ----------------
__device__ __forceinline__ void stage_chunk(
    uint32_t base, const __nv_bfloat16* __restrict__ Ahi, const __nv_bfloat16* __restrict__ Alo,
    const __nv_bfloat16* __restrict__ Bhi, const __nv_bfloat16* __restrict__ Blo,
    int tid, int m0, size_t brow0, int K, int kc)
{
    // A: 256 rows x 64 bf16 (hi+lo) = 2048 uint4 each; 512 threads -> 4 iters
#pragma unroll
    for (int i = 0; i < 4; i++) {
        int q = tid + i * 512;
        int m = q >> 3, kk = (q & 7) * 8;
        uint32_t d = base + m * PITCHB + kk * 2;
        size_t g = (size_t)(m0 + m) * K + kc + kk;
        CP16(d + S_AHI, Ahi + g);
        CP16(d + S_ALO, Alo + g);
    }
    // B: 64 rows x 64 bf16 (hi+lo) = 512 uint4 each -> 1 iter
    {
        int q = tid;
        int n = q >> 3, kk = (q & 7) * 8;
        uint32_t d = base + n * PITCHB + kk * 2;
        size_t g = (brow0 + n) * K + kc + kk;
        CP16(d + S_BHI, Bhi + g);
        CP16(d + S_BLO, Blo + g);
    }
}

// ---------------- HMMA bf16 hi/lo GEMM (pipelined, ldmatrix, BM=256) ----------------
__global__ __launch_bounds__(512, 1)
void mma_gemm(const __nv_bfloat16* __restrict__ Ahi, const __nv_bfloat16* __restrict__ Alo,
              const __nv_bfloat16* __restrict__ Bhi, const __nv_bfloat16* __restrict__ Blo,
              float* __restrict__ Y, int M, int K)
{
    extern __shared__ char smem[];
    const uint32_t sb32 = (uint32_t)__cvta_generic_to_shared(smem);

    const int tid = threadIdx.x;
    const int wid = tid >> 5, lane = tid & 31;
    const int gid = lane >> 2, t4 = lane & 3;
    const int wm = (wid >> 1) * 32;      // 0..224 (8 m-warps)
    const int wn = (wid & 1) * 32;       // 0 or 32
    const int b  = blockIdx.z;
    const int n0 = blockIdx.x * BN;
    const int m0 = blockIdx.y * BM;
    const size_t brow0 = (size_t)b * HWD + n0;

    const int lrow = lane & 15;
    const int lka  = (lane & 16) ? 16 : 0;
    const uint32_t aoff = (wm + lrow) * PITCHB + lka;
    const uint32_t boff = (wn + lrow) * PITCHB + lka;

    float acc[2][4][4];
#pragma unroll
    for (int i = 0; i < 2; i++)
#pragma unroll
        for (int j = 0; j < 4; j++)
#pragma unroll
            for (int c = 0; c < 4; c++) acc[i][j][c] = 0.f;

    stage_chunk(sb32, Ahi, Alo, Bhi, Blo, tid, m0, brow0, K, 0);
    CP_COMMIT();

    const int nc = K / BK;
    for (int ci = 0; ci < nc; ci++) {
        const uint32_t cur = sb32 + (ci & 1) * STAGE;
        if (ci + 1 < nc) {
            stage_chunk(sb32 + ((ci + 1) & 1) * STAGE, Ahi, Alo, Bhi, Blo,
                        tid, m0, brow0, K, (ci + 1) * BK);
            CP_COMMIT();
            CP_WAIT1();
        } else {
            CP_WAIT0();
        }
        __syncthreads();

#pragma unroll
        for (int k16 = 0; k16 < BK / 16; k16++) {
            const uint32_t kb2 = k16 * 32;
            uint32_t ah[2][4], al[2][4], bh[4][2], bl[4][2];
#pragma unroll
            for (int mt = 0; mt < 2; mt++) {
                uint32_t ad = cur + aoff + mt * 16 * PITCHB + kb2;
                LDSM_X4(ah[mt][0], ah[mt][1], ah[mt][2], ah[mt][3], ad + S_AHI);
                LDSM_X4(al[mt][0], al[mt][1], al[mt][2], al[mt][3], ad + S_ALO);
            }
#pragma unroll
            for (int pr = 0; pr < 2; pr++) {
                uint32_t bd = cur + boff + pr * 16 * PITCHB + kb2;
                LDSM_X4(bh[2*pr][0], bh[2*pr+1][0], bh[2*pr][1], bh[2*pr+1][1], bd + S_BHI);
                LDSM_X4(bl[2*pr][0], bl[2*pr+1][0], bl[2*pr][1], bl[2*pr+1][1], bd + S_BLO);
            }
#pragma unroll
            for (int mt = 0; mt < 2; mt++)
#pragma unroll
                for (int nt = 0; nt < 4; nt++) {
                    float* d = acc[mt][nt];
                    MMA_BF16(d[0],d[1],d[2],d[3], ah[mt][0],ah[mt][1],ah[mt][2],ah[mt][3], bh[nt][0],bh[nt][1]);
                    MMA_BF16(d[0],d[1],d[2],d[3], ah[mt][0],ah[mt][1],ah[mt][2],ah[mt][3], bl[nt][0],bl[nt][1]);
                    MMA_BF16(d[0],d[1],d[2],d[3], al[mt][0],al[mt][1],al[mt][2],al[mt][3], bh[nt][0],bh[nt][1]);
                }
        }
        __syncthreads();
    }

#pragma unroll
    for (int mt = 0; mt < 2; mt++) {
        int m = m0 + wm + mt * 16 + gid;
#pragma unroll
        for (int nt = 0; nt < 4; nt++) {
            int n = n0 + wn + nt * 8 + 2 * t4;
            float* d = acc[mt][nt];
            float* y0 = Y + ((size_t)b * M + m) * HWD + n;
            float* y1 = Y + ((size_t)b * M + m + 8) * HWD + n;
            *(float2*)y0 = make_float2(d[0], d[1]);
            *(float2*)y1 = make_float2(d[2], d[3]);
        }
    }
}

// ---------------- Local windowed attention (unchanged winner) ----------------
__global__ __launch_bounds__(512, 1)
void attn_kernel(const float* __restrict__ qh, const float* __restrict__ kh,
                 const float* __restrict__ vh,
                 __nv_bfloat16* __restrict__ ohi, __nv_bfloat16* __restrict__ olo)
{
    extern __shared__ float4 sm4[];

    const int tid = threadIdx.x;
    const int bz = blockIdx.z;
    const int b = bz >> 3;
    const int h = bz & 7;
    const int x0 = blockIdx.x * ATW - RAD;
    const int y0 = blockIdx.y * ATH - RAD;
    const size_t hbase = ((size_t)b * CO + (size_t)h * DK) * HWD;

    {
        const float* kb = kh + hbase;
        for (int pos = tid; pos < ANPOS; pos += 512) {
            int hy = pos / AHLW;
            int hx = pos - hy * AHLW;
            int yy = y0 + hy, xx = x0 + hx;
            if ((unsigned)yy < HH && (unsigned)xx < WW) {
                const float* g = kb + (size_t)yy * WW + xx;
#pragma unroll
                for (int c4 = 0; c4 < NC4; c4++) {
                    float4 t;
                    t.x = g[(size_t)(c4*4+0) * HWD];
                    t.y = g[(size_t)(c4*4+1) * HWD];
                    t.z = g[(size_t)(c4*4+2) * HWD];
                    t.w = g[(size_t)(c4*4+3) * HWD];
                    sm4[c4 * ANPOS + pos] = t;
                }
            } else {
                float4 z = {0.f, 0.f, 0.f, 0.f};
#pragma unroll
                for (int c4 = 0; c4 < NC4; c4++) sm4[c4 * ANPOS + pos] = z;
            }
        }
    }
    __syncthreads();

    const int tx = tid & 31;
    const int ty = tid >> 5;
    const int gx = blockIdx.x * ATW + tx;
    const int gy = blockIdx.y * ATH + ty;
    const size_t pbase = hbase + (size_t)gy * WW + gx;
    const int sb = ty * AHLW + tx;

    float sc[NN];
#pragma unroll
    for (int d = 0; d < NN; d++) sc[d] = 0.f;

    for (int c4 = 0; c4 < NC4; c4++) {
        float q0 = qh[pbase + (size_t)(c4*4+0) * HWD];
        float q1 = qh[pbase + (size_t)(c4*4+1) * HWD];
        float q2 = qh[pbase + (size_t)(c4*4+2) * HWD];
        float q3 = qh[pbase + (size_t)(c4*4+3) * HWD];
        const float4* kc = sm4 + c4 * ANPOS + sb;
#pragma unroll
        for (int dy = 0; dy < KER; dy++) {
#pragma unroll
            for (int dx = 0; dx < KER; dx++) {
                float4 k4 = kc[dy * AHLW + dx];
                int d = dy * KER + dx;
                sc[d] = fmaf(q0, k4.x, fmaf(q1, k4.y, fmaf(q2, k4.z, fmaf(q3, k4.w, sc[d]))));
            }
        }
    }
    __syncthreads();

    {
        const float* vb = vh + hbase;
        for (int pos = tid; pos < ANPOS; pos += 512) {
            int hy = pos / AHLW;
            int hx = pos - hy * AHLW;
            int yy = y0 + hy, xx = x0 + hx;
            if ((unsigned)yy < HH && (unsigned)xx < WW) {
                const float* g = vb + (size_t)yy * WW + xx;
#pragma unroll
                for (int c4 = 0; c4 < NC4; c4++) {
                    float4 t;
                    t.x = g[(size_t)(c4*4+0) * HWD];
                    t.y = g[(size_t)(c4*4+1) * HWD];
                    t.z = g[(size_t)(c4*4+2) * HWD];
                    t.w = g[(size_t)(c4*4+3) * HWD];
                    sm4[c4 * ANPOS + pos] = t;
                }
            } else {
                float4 z = {0.f, 0.f, 0.f, 0.f};
#pragma unroll
                for (int c4 = 0; c4 < NC4; c4++) sm4[c4 * ANPOS + pos] = z;
            }
        }
    }

    {
        const float invT = 0.125f;
        float mx = sc[0];
#pragma unroll
        for (int d = 1; d < NN; d++) mx = fmaxf(mx, sc[d]);
        float ssum = 0.f;
#pragma unroll
        for (int d = 0; d < NN; d++) {
            float e = __expf((sc[d] - mx) * invT);
            sc[d] = e;
            ssum += e;
        }
        float rinv = 1.f / ssum;
#pragma unroll
        for (int d = 0; d < NN; d++) sc[d] *= rinv;
    }
    __syncthreads();

    const size_t obase = ((size_t)b * HWD + (size_t)gy * WW + gx) * CO + (size_t)h * DK;
    for (int c4 = 0; c4 < NC4; c4++) {
        const float4* vc = sm4 + c4 * ANPOS + sb;
        float a0 = 0.f, a1 = 0.f, a2 = 0.f, a3 = 0.f;
#pragma unroll
        for (int dy = 0; dy < KER; dy++) {
#pragma unroll
            for (int dx = 0; dx < KER; dx++) {
                float4 v4 = vc[dy * AHLW + dx];
                float w = sc[dy * KER + dx];
                a0 = fmaf(w, v4.x, a0);
                a1 = fmaf(w, v4.y, a1);
                a2 = fmaf(w, v4.z, a2);
                a3 = fmaf(w, v4.w, a3);
            }
        }
        __nv_bfloat16 h0 = __float2bfloat16(a0), h1 = __float2bfloat16(a1);
        __nv_bfloat16 h2 = __float2bfloat16(a2), h3 = __float2bfloat16(a3);
        *(__nv_bfloat162*)(ohi + obase + c4*4)     = __halves2bfloat162(h0, h1);
        *(__nv_bfloat162*)(ohi + obase + c4*4 + 2) = __halves2bfloat162(h2, h3);
        *(__nv_bfloat162*)(olo + obase + c4*4)     = __halves2bfloat162(
            __float2bfloat16(a0 - __bfloat162float(h0)),
            __float2bfloat16(a1 - __bfloat162float(h1)));
        *(__nv_bfloat162*)(olo + obase + c4*4 + 2) = __halves2bfloat162(
            __float2bfloat16(a2 - __bfloat162float(h2)),
            __float2bfloat16(a3 - __bfloat162float(h3)));
    }
}

// ---------------- residual + LayerNorm2d ----------------
__global__ __launch_bounds__(256)
void ln_kernel(const float* __restrict__ fc, const float* __restrict__ res,
               const float* __restrict__ lnw, const float* __restrict__ lnb,
               float* __restrict__ out)
{
    int p = blockIdx.x * 256 + threadIdx.x;
    int b = p / HWD;
    int pp = p - b * HWD;
    const float* f = fc + (size_t)b * CC * HWD + pp;
    const float* r = res + (size_t)b * CC * HWD + pp;

    float s = 0.f, s2 = 0.f;
#pragma unroll 4
    for (int c = 0; c < CC; c++) {
        float v = f[(size_t)c * HWD] + r[(size_t)c * HWD];
        s += v;
        s2 = fmaf(v, v, s2);
    }
    float mu = s * (1.f / CC);
    float var = s2 * (1.f / CC) - mu * mu;
    float inv = rsqrtf(var + LN_EPS);

    float* o = out + (size_t)b * CC * HWD + pp;
#pragma unroll 4
    for (int c = 0; c < CC; c++) {
        float v = f[(size_t)c * HWD] + r[(size_t)c * HWD];
        o[(size_t)c * HWD] = lnw[c] * ((v - mu) * inv) + lnb[c];
    }
}

// ---------------- launch ----------------
extern "C" void kernel_launch(void* const* d_in, const int* in_sizes, int n_in,
                              void* d_out, int out_size)
{
    const float* q   = (const float*)d_in[0];
    const float* k   = (const float*)d_in[1];
    const float* v   = (const float*)d_in[2];
    const float* Wq  = (const float*)d_in[3];
    const float* Wk  = (const float*)d_in[4];
    const float* Wv  = (const float*)d_in[5];
    const float* Wfc = (const float*)d_in[6];
    const float* lnw = (const float*)d_in[7];
    const float* lnb = (const float*)d_in[8];

    float *qh, *kh, *vh;
    __nv_bfloat16 *xhi, *xlo, *atthi, *attlo, *whi, *wlo;
    cudaGetSymbolAddress((void**)&qh, g_qh);
    cudaGetSymbolAddress((void**)&kh, g_kh);
    cudaGetSymbolAddress((void**)&vh, g_vh);
    cudaGetSymbolAddress((void**)&xhi, g_xhi);
    cudaGetSymbolAddress((void**)&xlo, g_xlo);
    cudaGetSymbolAddress((void**)&atthi, g_atthi);
    cudaGetSymbolAddress((void**)&attlo, g_attlo);
    cudaGetSymbolAddress((void**)&whi, g_whi);
    cudaGetSymbolAddress((void**)&wlo, g_wlo);
    float* fcb = qh;

    const size_t NX = (size_t)BB * CC * HWD;
    const int NW = CO * CC;

    cudaFuncSetAttribute(mma_gemm, cudaFuncAttributeMaxDynamicSharedMemorySize, GEMM_SMEM);

    // launch order chosen so the 6th launch (ncu -s 5 -c 1) is mma_gemm
    split_kernel<<<NW / 1024, 256>>>(Wq,  whi + 0*NW, wlo + 0*NW, NW);   // 1
    split_kernel<<<NW / 1024, 256>>>(Wk,  whi + 1*NW, wlo + 1*NW, NW);   // 2
    split_kernel<<<NW / 1024, 256>>>(Wv,  whi + 2*NW, wlo + 2*NW, NW);   // 3
    split_kernel<<<NW / 1024, 256>>>(Wfc, whi + 3*NW, wlo + 3*NW, NW);   // 4

    dim3 tg(HWD / 32, CC / 32, BB);
    dim3 gp(HWD / BN, CO / BM, BB);
    tsplit_kernel<<<tg, 256>>>(q, xhi + 0*NX, xlo + 0*NX);               // 5
    mma_gemm<<<gp, 512, GEMM_SMEM>>>(whi + 0*NW, wlo + 0*NW, xhi + 0*NX, xlo + 0*NX, qh, CO, CC);  // 6 <- profiled
    tsplit_kernel<<<tg, 256>>>(k, xhi + 1*NX, xlo + 1*NX);
    mma_gemm<<<gp, 512, GEMM_SMEM>>>(whi + 1*NW, wlo + 1*NW, xhi + 1*NX, xlo + 1*NX, kh, CO, CC);
    tsplit_kernel<<<tg, 256>>>(v, xhi + 2*NX, xlo + 2*NX);
    mma_gemm<<<gp, 512, GEMM_SMEM>>>(whi + 2*NW, wlo + 2*NW, xhi + 2*NX, xlo + 2*NX, vh, CO, CC);

    int smem = NC4 * ANPOS * (int)sizeof(float4);
    cudaFuncSetAttribute(attn_kernel, cudaFuncAttributeMaxDynamicSharedMemorySize, smem);
    dim3 ga(WW / ATW, HH / ATH, BB * NHEAD);
    attn_kernel<<<ga, 512, smem>>>(qh, kh, vh, atthi, attlo);

    dim3 gf(HWD / BN, CC / BM, BB);
    mma_gemm<<<gf, 512, GEMM_SMEM>>>(whi + 3*NW, wlo + 3*NW, atthi, attlo, fcb, CC, CO);

    ln_kernel<<<(BB * HWD) / 256, 256>>>(fcb, q, lnw, lnb, (float*)d_out);
}

// round 15
// speedup vs baseline: 1.0699x; 1.0699x over previous
#include <cuda_runtime.h>
#include <cuda_bf16.h>
#include <cstdint>

#define BB 4
#define CC 256
#define HH 128
#define WW 128
#define HWD (HH*WW)
#define NHEAD 8
#define DK 64
#define CO 512
#define KER 7
#define RAD 3
#define NN 49
#define LN_EPS 1e-6f

// attention tile
#define ATW 32
#define ATH 16
#define AHLW (ATW + 2*RAD)   // 38
#define AHLH (ATH + 2*RAD)   // 22
#define ANPOS (AHLW*AHLH)    // 836
#define NC4 (DK/4)

// HMMA GEMM tiles (R11 winning config)
#define BM 128
#define BN 64
#define BK 64
#define PITCHB 144           // bytes per 64-bf16 row: 9x16B -> conflict-free LDSM
// per-stage smem byte offsets
#define S_AHI 0
#define S_ALO (BM*PITCHB)            // 18432
#define S_BHI (2*BM*PITCHB)          // 36864
#define S_BLO (2*BM*PITCHB + BN*PITCHB)
#define STAGE (2*BM*PITCHB + 2*BN*PITCHB)   // 55296
#define GEMM_SMEM (2*STAGE)                  // 110592

typedef unsigned long long u64;

// ---------------- scratch ----------------
__device__ float g_qh[33554432];
__device__ float g_kh[33554432];
__device__ float g_vh[33554432];
__device__ __nv_bfloat16 g_xhi[3][16777216];
__device__ __nv_bfloat16 g_xlo[3][16777216];
__device__ __nv_bfloat16 g_atthi[33554432];
__device__ __nv_bfloat16 g_attlo[33554432];
__device__ __nv_bfloat16 g_whi[524288];
__device__ __nv_bfloat16 g_wlo[524288];

// ---------------- PTX helpers ----------------
#define MMA_BF16(d0,d1,d2,d3, a0,a1,a2,a3, b0,b1) \
    asm volatile("mma.sync.aligned.m16n8k16.row.col.f32.bf16.bf16.f32 " \
        "{%0,%1,%2,%3}, {%4,%5,%6,%7}, {%8,%9}, {%0,%1,%2,%3};" \
        : "+f"(d0), "+f"(d1), "+f"(d2), "+f"(d3) \
        : "r"(a0), "r"(a1), "r"(a2), "r"(a3), "r"(b0), "r"(b1))

#define LDSM_X4(r0,r1,r2,r3, addr) \
    asm volatile("ldmatrix.sync.aligned.m8n8.x4.shared.b16 {%0,%1,%2,%3}, [%4];" \
        : "=r"(r0),"=r"(r1),"=r"(r2),"=r"(r3) : "r"(addr))

#define CP16(dst, src) \
    asm volatile("cp.async.cg.shared.global [%0], [%1], 16;" :: "r"(dst), "l"(src))
#define CP_COMMIT() asm volatile("cp.async.commit_group;")
#define CP_WAIT1()  asm volatile("cp.async.wait_group 1;")
#define CP_WAIT0()  asm volatile("cp.async.wait_group 0;")

// ---------------- element-wise fp32 -> bf16 hi/lo split (weights) ----------------
__global__ __launch_bounds__(256)
void split_kernel(const float* __restrict__ x, __nv_bfloat16* __restrict__ hi,
                  __nv_bfloat16* __restrict__ lo, int n)
{
    int i = (blockIdx.x * 256 + threadIdx.x) * 4;
    if (i >= n) return;
    float4 v = *(const float4*)(x + i);
    __nv_bfloat16 h0 = __float2bfloat16(v.x), h1 = __float2bfloat16(v.y);
    __nv_bfloat16 h2 = __float2bfloat16(v.z), h3 = __float2bfloat16(v.w);
    __nv_bfloat16 l0 = __float2bfloat16(v.x - __bfloat162float(h0));
    __nv_bfloat16 l1 = __float2bfloat16(v.y - __bfloat162float(h1));
    __nv_bfloat16 l2 = __float2bfloat16(v.z - __bfloat162float(h2));
    __nv_bfloat16 l3 = __float2bfloat16(v.w - __bfloat162float(h3));
    __nv_bfloat162* H = (__nv_bfloat162*)(hi + i);
    __nv_bfloat162* L = (__nv_bfloat162*)(lo + i);
    H[0] = __halves2bfloat162(h0, h1); H[1] = __halves2bfloat162(h2, h3);
    L[0] = __halves2bfloat162(l0, l1); L[1] = __halves2bfloat162(l2, l3);
}

// ---------------- transpose + split: X[b][c][p] -> X^T[b][p][c] bf16 hi/lo ----------------
__global__ __launch_bounds__(256)
void tsplit_kernel(const float* __restrict__ x, __nv_bfloat16* __restrict__ hi,
                   __nv_bfloat16* __restrict__ lo)
{
    __shared__ float t[32][33];
    int b = blockIdx.z, c0 = blockIdx.y * 32, p0 = blockIdx.x * 32;
    int tx = threadIdx.x & 31, ty = threadIdx.x >> 5;
    const float* src = x + ((size_t)b * CC + c0) * HWD + p0;
#pragma unroll
    for (int j = 0; j < 4; j++)
        t[ty + 8*j][tx] = src[(size_t)(ty + 8*j) * HWD + tx];
    __syncthreads();
#pragma unroll
    for (int j = 0; j < 4; j++) {
        float v = t[tx][ty + 8*j];
        size_t o = ((size_t)b * HWD + p0 + ty + 8*j) * CC + c0 + tx;
        __nv_bfloat16 hv = __float2bfloat16(v);
        hi[o] = hv;
        lo[o] = __float2bfloat16(v - __bfloat162float(hv));
    }
}

// ---------------- staging: one K-chunk into stage buffer via cp.async ----------------
__device__ __forceinline__ void stage_chunk(
    uint32_t base, const __nv_bfloat16* __restrict__ Ahi, const __nv_bfloat16* __restrict__ Alo,
    const __nv_bfloat16* __restrict__ Bhi, const __nv_bfloat16* __restrict__ Blo,
    int tid, int m0, size_t brow0, int K, int kc)
{
#pragma unroll
    for (int i = 0; i < 4; i++) {
        int q = tid + i * 256;
        int m = q >> 3, kk = (q & 7) * 8;
        uint32_t d = base + m * PITCHB + kk * 2;
        size_t g = (size_t)(m0 + m) * K + kc + kk;
        CP16(d + S_AHI, Ahi + g);
        CP16(d + S_ALO, Alo + g);
    }
#pragma unroll
    for (int i = 0; i < 2; i++) {
        int q = tid + i * 256;
        int n = q >> 3, kk = (q & 7) * 8;
        uint32_t d = base + n * PITCHB + kk * 2;
        size_t g = (brow0 + n) * K + kc + kk;
        CP16(d + S_BHI, Bhi + g);
        CP16(d + S_BLO, Blo + g);
    }
}

// ---------------- HMMA bf16 hi/lo GEMM (R11 winner; m varies fastest in grid) ----------------
__global__ __launch_bounds__(256, 2)
void mma_gemm(const __nv_bfloat16* __restrict__ Ahi, const __nv_bfloat16* __restrict__ Alo,
              const __nv_bfloat16* __restrict__ Bhi, const __nv_bfloat16* __restrict__ Blo,
              float* __restrict__ Y, int M, int K)
{
    extern __shared__ char smem[];
    const uint32_t sb32 = (uint32_t)__cvta_generic_to_shared(smem);

    const int tid = threadIdx.x;
    const int wid = tid >> 5, lane = tid & 31;
    const int gid = lane >> 2, t4 = lane & 3;
    const int wm = (wid >> 1) * 32;
    const int wn = (wid & 1) * 32;
    const int b  = blockIdx.z;
    // m on blockIdx.x (fastest): CTAs sharing one B tile are co-scheduled -> B L2 reuse
    const int m0 = blockIdx.x * BM;
    const int n0 = blockIdx.y * BN;
    const size_t brow0 = (size_t)b * HWD + n0;

    const int lrow = lane & 15;
    const int lka  = (lane & 16) ? 16 : 0;
    const uint32_t aoff = (wm + lrow) * PITCHB + lka;
    const uint32_t boff = (wn + lrow) * PITCHB + lka;

    float acc[2][4][4];
#pragma unroll
    for (int i = 0; i < 2; i++)
#pragma unroll
        for (int j = 0; j < 4; j++)
#pragma unroll
            for (int c = 0; c < 4; c++) acc[i][j][c] = 0.f;

    stage_chunk(sb32, Ahi, Alo, Bhi, Blo, tid, m0, brow0, K, 0);
    CP_COMMIT();

    const int nc = K / BK;
    for (int ci = 0; ci < nc; ci++) {
        const uint32_t cur = sb32 + (ci & 1) * STAGE;
        if (ci + 1 < nc) {
            stage_chunk(sb32 + ((ci + 1) & 1) * STAGE, Ahi, Alo, Bhi, Blo,
                        tid, m0, brow0, K, (ci + 1) * BK);
            CP_COMMIT();
            CP_WAIT1();
        } else {
            CP_WAIT0();
        }
        __syncthreads();

#pragma unroll
        for (int k16 = 0; k16 < BK / 16; k16++) {
            const uint32_t kb2 = k16 * 32;
            uint32_t ah[2][4], al[2][4], bh[4][2], bl[4][2];
#pragma unroll
            for (int mt = 0; mt < 2; mt++) {
                uint32_t ad = cur + aoff + mt * 16 * PITCHB + kb2;
                LDSM_X4(ah[mt][0], ah[mt][1], ah[mt][2], ah[mt][3], ad + S_AHI);
                LDSM_X4(al[mt][0], al[mt][1], al[mt][2], al[mt][3], ad + S_ALO);
            }
#pragma unroll
            for (int pr = 0; pr < 2; pr++) {
                uint32_t bd = cur + boff + pr * 16 * PITCHB + kb2;
                LDSM_X4(bh[2*pr][0], bh[2*pr+1][0], bh[2*pr][1], bh[2*pr+1][1], bd + S_BHI);
                LDSM_X4(bl[2*pr][0], bl[2*pr+1][0], bl[2*pr][1], bl[2*pr+1][1], bd + S_BLO);
            }
#pragma unroll
            for (int mt = 0; mt < 2; mt++)
#pragma unroll
                for (int nt = 0; nt < 4; nt++) {
                    float* d = acc[mt][nt];
                    MMA_BF16(d[0],d[1],d[2],d[3], ah[mt][0],ah[mt][1],ah[mt][2],ah[mt][3], bh[nt][0],bh[nt][1]);
                    MMA_BF16(d[0],d[1],d[2],d[3], ah[mt][0],ah[mt][1],ah[mt][2],ah[mt][3], bl[nt][0],bl[nt][1]);
                    MMA_BF16(d[0],d[1],d[2],d[3], al[mt][0],al[mt][1],al[mt][2],al[mt][3], bh[nt][0],bh[nt][1]);
                }
        }
        __syncthreads();
    }

#pragma unroll
    for (int mt = 0; mt < 2; mt++) {
        int m = m0 + wm + mt * 16 + gid;
#pragma unroll
        for (int nt = 0; nt < 4; nt++) {
            int n = n0 + wn + nt * 8 + 2 * t4;
            float* d = acc[mt][nt];
            float* y0 = Y + ((size_t)b * M + m) * HWD + n;
            float* y1 = Y + ((size_t)b * M + m + 8) * HWD + n;
            *(float2*)y0 = make_float2(d[0], d[1]);
            *(float2*)y1 = make_float2(d[2], d[3]);
        }
    }
}

// ---------------- Local windowed attention (unchanged winner) ----------------
__global__ __launch_bounds__(512, 1)
void attn_kernel(const float* __restrict__ qh, const float* __restrict__ kh,
                 const float* __restrict__ vh,
                 __nv_bfloat16* __restrict__ ohi, __nv_bfloat16* __restrict__ olo)
{
    extern __shared__ float4 sm4[];

    const int tid = threadIdx.x;
    const int bz = blockIdx.z;
    const int b = bz >> 3;
    const int h = bz & 7;
    const int x0 = blockIdx.x * ATW - RAD;
    const int y0 = blockIdx.y * ATH - RAD;
    const size_t hbase = ((size_t)b * CO + (size_t)h * DK) * HWD;

    {
        const float* kb = kh + hbase;
        for (int pos = tid; pos < ANPOS; pos += 512) {
            int hy = pos / AHLW;
            int hx = pos - hy * AHLW;
            int yy = y0 + hy, xx = x0 + hx;
            if ((unsigned)yy < HH && (unsigned)xx < WW) {
                const float* g = kb + (size_t)yy * WW + xx;
#pragma unroll
                for (int c4 = 0; c4 < NC4; c4++) {
                    float4 t;
                    t.x = g[(size_t)(c4*4+0) * HWD];
                    t.y = g[(size_t)(c4*4+1) * HWD];
                    t.z = g[(size_t)(c4*4+2) * HWD];
                    t.w = g[(size_t)(c4*4+3) * HWD];
                    sm4[c4 * ANPOS + pos] = t;
                }
            } else {
                float4 z = {0.f, 0.f, 0.f, 0.f};
#pragma unroll
                for (int c4 = 0; c4 < NC4; c4++) sm4[c4 * ANPOS + pos] = z;
            }
        }
    }
    __syncthreads();

    const int tx = tid & 31;
    const int ty = tid >> 5;
    const int gx = blockIdx.x * ATW + tx;
    const int gy = blockIdx.y * ATH + ty;
    const size_t pbase = hbase + (size_t)gy * WW + gx;
    const int sb = ty * AHLW + tx;

    float sc[NN];
#pragma unroll
    for (int d = 0; d < NN; d++) sc[d] = 0.f;

    for (int c4 = 0; c4 < NC4; c4++) {
        float q0 = qh[pbase + (size_t)(c4*4+0) * HWD];
        float q1 = qh[pbase + (size_t)(c4*4+1) * HWD];
        float q2 = qh[pbase + (size_t)(c4*4+2) * HWD];
        float q3 = qh[pbase + (size_t)(c4*4+3) * HWD];
        const float4* kc = sm4 + c4 * ANPOS + sb;
#pragma unroll
        for (int dy = 0; dy < KER; dy++) {
#pragma unroll
            for (int dx = 0; dx < KER; dx++) {
                float4 k4 = kc[dy * AHLW + dx];
                int d = dy * KER + dx;
                sc[d] = fmaf(q0, k4.x, fmaf(q1, k4.y, fmaf(q2, k4.z, fmaf(q3, k4.w, sc[d]))));
            }
        }
    }
    __syncthreads();

    {
        const float* vb = vh + hbase;
        for (int pos = tid; pos < ANPOS; pos += 512) {
            int hy = pos / AHLW;
            int hx = pos - hy * AHLW;
            int yy = y0 + hy, xx = x0 + hx;
            if ((unsigned)yy < HH && (unsigned)xx < WW) {
                const float* g = vb + (size_t)yy * WW + xx;
#pragma unroll
                for (int c4 = 0; c4 < NC4; c4++) {
                    float4 t;
                    t.x = g[(size_t)(c4*4+0) * HWD];
                    t.y = g[(size_t)(c4*4+1) * HWD];
                    t.z = g[(size_t)(c4*4+2) * HWD];
                    t.w = g[(size_t)(c4*4+3) * HWD];
                    sm4[c4 * ANPOS + pos] = t;
                }
            } else {
                float4 z = {0.f, 0.f, 0.f, 0.f};
#pragma unroll
                for (int c4 = 0; c4 < NC4; c4++) sm4[c4 * ANPOS + pos] = z;
            }
        }
    }

    {
        const float invT = 0.125f;
        float mx = sc[0];
#pragma unroll
        for (int d = 1; d < NN; d++) mx = fmaxf(mx, sc[d]);
        float ssum = 0.f;
#pragma unroll
        for (int d = 0; d < NN; d++) {
            float e = __expf((sc[d] - mx) * invT);
            sc[d] = e;
            ssum += e;
        }
        float rinv = 1.f / ssum;
#pragma unroll
        for (int d = 0; d < NN; d++) sc[d] *= rinv;
    }
    __syncthreads();

    const size_t obase = ((size_t)b * HWD + (size_t)gy * WW + gx) * CO + (size_t)h * DK;
    for (int c4 = 0; c4 < NC4; c4++) {
        const float4* vc = sm4 + c4 * ANPOS + sb;
        float a0 = 0.f, a1 = 0.f, a2 = 0.f, a3 = 0.f;
#pragma unroll
        for (int dy = 0; dy < KER; dy++) {
#pragma unroll
            for (int dx = 0; dx < KER; dx++) {
                float4 v4 = vc[dy * AHLW + dx];
                float w = sc[dy * KER + dx];
                a0 = fmaf(w, v4.x, a0);
                a1 = fmaf(w, v4.y, a1);
                a2 = fmaf(w, v4.z, a2);
                a3 = fmaf(w, v4.w, a3);
            }
        }
        __nv_bfloat16 h0 = __float2bfloat16(a0), h1 = __float2bfloat16(a1);
        __nv_bfloat16 h2 = __float2bfloat16(a2), h3 = __float2bfloat16(a3);
        *(__nv_bfloat162*)(ohi + obase + c4*4)     = __halves2bfloat162(h0, h1);
        *(__nv_bfloat162*)(ohi + obase + c4*4 + 2) = __halves2bfloat162(h2, h3);
        *(__nv_bfloat162*)(olo + obase + c4*4)     = __halves2bfloat162(
            __float2bfloat16(a0 - __bfloat162float(h0)),
            __float2bfloat16(a1 - __bfloat162float(h1)));
        *(__nv_bfloat162*)(olo + obase + c4*4 + 2) = __halves2bfloat162(
            __float2bfloat16(a2 - __bfloat162float(h2)),
            __float2bfloat16(a3 - __bfloat162float(h3)));
    }
}

// ---------------- residual + LayerNorm2d ----------------
__global__ __launch_bounds__(256)
void ln_kernel(const float* __restrict__ fc, const float* __restrict__ res,
               const float* __restrict__ lnw, const float* __restrict__ lnb,
               float* __restrict__ out)
{
    int p = blockIdx.x * 256 + threadIdx.x;
    int b = p / HWD;
    int pp = p - b * HWD;
    const float* f = fc + (size_t)b * CC * HWD + pp;
    const float* r = res + (size_t)b * CC * HWD + pp;

    float s = 0.f, s2 = 0.f;
#pragma unroll 4
    for (int c = 0; c < CC; c++) {
        float v = f[(size_t)c * HWD] + r[(size_t)c * HWD];
        s += v;
        s2 = fmaf(v, v, s2);
    }
    float mu = s * (1.f / CC);
    float var = s2 * (1.f / CC) - mu * mu;
    float inv = rsqrtf(var + LN_EPS);

    float* o = out + (size_t)b * CC * HWD + pp;
#pragma unroll 4
    for (int c = 0; c < CC; c++) {
        float v = f[(size_t)c * HWD] + r[(size_t)c * HWD];
        o[(size_t)c * HWD] = lnw[c] * ((v - mu) * inv) + lnb[c];
    }
}

// ---------------- launch ----------------
extern "C" void kernel_launch(void* const* d_in, const int* in_sizes, int n_in,
                              void* d_out, int out_size)
{
    const float* q   = (const float*)d_in[0];
    const float* k   = (const float*)d_in[1];
    const float* v   = (const float*)d_in[2];
    const float* Wq  = (const float*)d_in[3];
    const float* Wk  = (const float*)d_in[4];
    const float* Wv  = (const float*)d_in[5];
    const float* Wfc = (const float*)d_in[6];
    const float* lnw = (const float*)d_in[7];
    const float* lnb = (const float*)d_in[8];

    float *qh, *kh, *vh;
    __nv_bfloat16 *xhi, *xlo, *atthi, *attlo, *whi, *wlo;
    cudaGetSymbolAddress((void**)&qh, g_qh);
    cudaGetSymbolAddress((void**)&kh, g_kh);
    cudaGetSymbolAddress((void**)&vh, g_vh);
    cudaGetSymbolAddress((void**)&xhi, g_xhi);
    cudaGetSymbolAddress((void**)&xlo, g_xlo);
    cudaGetSymbolAddress((void**)&atthi, g_atthi);
    cudaGetSymbolAddress((void**)&attlo, g_attlo);
    cudaGetSymbolAddress((void**)&whi, g_whi);
    cudaGetSymbolAddress((void**)&wlo, g_wlo);
    float* fcb = qh;

    const size_t NX = (size_t)BB * CC * HWD;
    const int NW = CO * CC;

    dim3 tg(HWD / 32, CC / 32, BB);
    tsplit_kernel<<<tg, 256>>>(q, xhi + 0*NX, xlo + 0*NX);
    tsplit_kernel<<<tg, 256>>>(k, xhi + 1*NX, xlo + 1*NX);
    tsplit_kernel<<<tg, 256>>>(v, xhi + 2*NX, xlo + 2*NX);
    split_kernel<<<NW / 1024, 256>>>(Wq,  whi + 0*NW, wlo + 0*NW, NW);
    split_kernel<<<NW / 1024, 256>>>(Wk,  whi + 1*NW, wlo + 1*NW, NW);
    split_kernel<<<NW / 1024, 256>>>(Wv,  whi + 2*NW, wlo + 2*NW, NW);
    split_kernel<<<NW / 1024, 256>>>(Wfc, whi + 3*NW, wlo + 3*NW, NW);

    cudaFuncSetAttribute(mma_gemm, cudaFuncAttributeMaxDynamicSharedMemorySize, GEMM_SMEM);

    // grid: x = m-blocks (fastest) so CTAs sharing a B tile run concurrently
    dim3 gp(CO / BM, HWD / BN, BB);
    mma_gemm<<<gp, 256, GEMM_SMEM>>>(whi + 0*NW, wlo + 0*NW, xhi + 0*NX, xlo + 0*NX, qh, CO, CC);
    mma_gemm<<<gp, 256, GEMM_SMEM>>>(whi + 1*NW, wlo + 1*NW, xhi + 1*NX, xlo + 1*NX, kh, CO, CC);
    mma_gemm<<<gp, 256, GEMM_SMEM>>>(whi + 2*NW, wlo + 2*NW, xhi + 2*NX, xlo + 2*NX, vh, CO, CC);

    int smem = NC4 * ANPOS * (int)sizeof(float4);
    cudaFuncSetAttribute(attn_kernel, cudaFuncAttributeMaxDynamicSharedMemorySize, smem);
    dim3 ga(WW / ATW, HH / ATH, BB * NHEAD);
    attn_kernel<<<ga, 512, smem>>>(qh, kh, vh, atthi, attlo);

    dim3 gf(CC / BM, HWD / BN, BB);
    mma_gemm<<<gf, 256, GEMM_SMEM>>>(whi + 3*NW, wlo + 3*NW, atthi, attlo, fcb, CC, CO);

    ln_kernel<<<(BB * HWD) / 256, 256>>>(fcb, q, lnw, lnb, (float*)d_out);
}

// round 16
// speedup vs baseline: 1.0748x; 1.0046x over previous
#include <cuda_runtime.h>
#include <cuda_bf16.h>
#include <cstdint>

#define BB 4
#define CC 256
#define HH 128
#define WW 128
#define HWD (HH*WW)
#define NHEAD 8
#define DK 64
#define CO 512
#define KER 7
#define RAD 3
#define NN 49
#define LN_EPS 1e-6f

// attention tile
#define ATW 32
#define ATH 16
#define AHLW (ATW + 2*RAD)   // 38
#define AHLH (ATH + 2*RAD)   // 22
#define ANPOS (AHLW*AHLH)    // 836
#define NC4 (DK/4)

// HMMA GEMM tiles (R11 winning config)
#define BM 128
#define BN 64
#define BK 64
#define PITCHB 144           // bytes per 64-bf16 row: 9x16B -> conflict-free LDSM
// per-stage smem byte offsets
#define S_AHI 0
#define S_ALO (BM*PITCHB)            // 18432
#define S_BHI (2*BM*PITCHB)          // 36864
#define S_BLO (2*BM*PITCHB + BN*PITCHB)
#define STAGE (2*BM*PITCHB + 2*BN*PITCHB)   // 55296
#define GEMM_SMEM (2*STAGE)                  // 110592

typedef unsigned long long u64;

// ---------------- scratch ----------------
__device__ float g_qh[33554432];
__device__ float g_kh[33554432];
__device__ float g_vh[33554432];
__device__ __nv_bfloat16 g_xhi[3][16777216];
__device__ __nv_bfloat16 g_xlo[3][16777216];
__device__ __nv_bfloat16 g_atthi[33554432];
__device__ __nv_bfloat16 g_attlo[33554432];
__device__ __nv_bfloat16 g_whi[524288];
__device__ __nv_bfloat16 g_wlo[524288];

// ---------------- PTX helpers ----------------
#define MMA_BF16(d0,d1,d2,d3, a0,a1,a2,a3, b0,b1) \
    asm volatile("mma.sync.aligned.m16n8k16.row.col.f32.bf16.bf16.f32 " \
        "{%0,%1,%2,%3}, {%4,%5,%6,%7}, {%8,%9}, {%0,%1,%2,%3};" \
        : "+f"(d0), "+f"(d1), "+f"(d2), "+f"(d3) \
        : "r"(a0), "r"(a1), "r"(a2), "r"(a3), "r"(b0), "r"(b1))

#define LDSM_X4(r0,r1,r2,r3, addr) \
    asm volatile("ldmatrix.sync.aligned.m8n8.x4.shared.b16 {%0,%1,%2,%3}, [%4];" \
        : "=r"(r0),"=r"(r1),"=r"(r2),"=r"(r3) : "r"(addr))

#define CP16(dst, src) \
    asm volatile("cp.async.cg.shared.global [%0], [%1], 16;" :: "r"(dst), "l"(src))
#define CP_COMMIT() asm volatile("cp.async.commit_group;")
#define CP_WAIT1()  asm volatile("cp.async.wait_group 1;")
#define CP_WAIT0()  asm volatile("cp.async.wait_group 0;")

// ---------------- element-wise fp32 -> bf16 hi/lo split (weights) ----------------
__global__ __launch_bounds__(256)
void split_kernel(const float* __restrict__ x, __nv_bfloat16* __restrict__ hi,
                  __nv_bfloat16* __restrict__ lo, int n)
{
    int i = (blockIdx.x * 256 + threadIdx.x) * 4;
    if (i >= n) return;
    float4 v = *(const float4*)(x + i);
    __nv_bfloat16 h0 = __float2bfloat16(v.x), h1 = __float2bfloat16(v.y);
    __nv_bfloat16 h2 = __float2bfloat16(v.z), h3 = __float2bfloat16(v.w);
    __nv_bfloat16 l0 = __float2bfloat16(v.x - __bfloat162float(h0));
    __nv_bfloat16 l1 = __float2bfloat16(v.y - __bfloat162float(h1));
    __nv_bfloat16 l2 = __float2bfloat16(v.z - __bfloat162float(h2));
    __nv_bfloat16 l3 = __float2bfloat16(v.w - __bfloat162float(h3));
    __nv_bfloat162* H = (__nv_bfloat162*)(hi + i);
    __nv_bfloat162* L = (__nv_bfloat162*)(lo + i);
    H[0] = __halves2bfloat162(h0, h1); H[1] = __halves2bfloat162(h2, h3);
    L[0] = __halves2bfloat162(l0, l1); L[1] = __halves2bfloat162(l2, l3);
}

// ---------------- transpose + split: X[b][c][p] -> X^T[b][p][c] bf16 hi/lo ----------------
__global__ __launch_bounds__(256)
void tsplit_kernel(const float* __restrict__ x, __nv_bfloat16* __restrict__ hi,
                   __nv_bfloat16* __restrict__ lo)
{
    __shared__ float t[32][33];
    int b = blockIdx.z, c0 = blockIdx.y * 32, p0 = blockIdx.x * 32;
    int tx = threadIdx.x & 31, ty = threadIdx.x >> 5;
    const float* src = x + ((size_t)b * CC + c0) * HWD + p0;
#pragma unroll
    for (int j = 0; j < 4; j++)
        t[ty + 8*j][tx] = src[(size_t)(ty + 8*j) * HWD + tx];
    __syncthreads();
#pragma unroll
    for (int j = 0; j < 4; j++) {
        float v = t[tx][ty + 8*j];
        size_t o = ((size_t)b * HWD + p0 + ty + 8*j) * CC + c0 + tx;
        __nv_bfloat16 hv = __float2bfloat16(v);
        hi[o] = hv;
        lo[o] = __float2bfloat16(v - __bfloat162float(hv));
    }
}

// ---------------- staging: one K-chunk into stage buffer via cp.async ----------------
__device__ __forceinline__ void stage_chunk(
    uint32_t base, const __nv_bfloat16* __restrict__ Ahi, const __nv_bfloat16* __restrict__ Alo,
    const __nv_bfloat16* __restrict__ Bhi, const __nv_bfloat16* __restrict__ Blo,
    int tid, int m0, size_t brow0, int K, int kc)
{
#pragma unroll
    for (int i = 0; i < 4; i++) {
        int q = tid + i * 256;
        int m = q >> 3, kk = (q & 7) * 8;
        uint32_t d = base + m * PITCHB + kk * 2;
        size_t g = (size_t)(m0 + m) * K + kc + kk;
        CP16(d + S_AHI, Ahi + g);
        CP16(d + S_ALO, Alo + g);
    }
#pragma unroll
    for (int i = 0; i < 2; i++) {
        int q = tid + i * 256;
        int n = q >> 3, kk = (q & 7) * 8;
        uint32_t d = base + n * PITCHB + kk * 2;
        size_t g = (brow0 + n) * K + kc + kk;
        CP16(d + S_BHI, Bhi + g);
        CP16(d + S_BLO, Blo + g);
    }
}

// ---------------- HMMA bf16 hi/lo GEMM (R11 winner; m varies fastest in grid) ----------------
__global__ __launch_bounds__(256, 2)
void mma_gemm(const __nv_bfloat16* __restrict__ Ahi, const __nv_bfloat16* __restrict__ Alo,
              const __nv_bfloat16* __restrict__ Bhi, const __nv_bfloat16* __restrict__ Blo,
              float* __restrict__ Y, int M, int K)
{
    extern __shared__ char smem[];
    const uint32_t sb32 = (uint32_t)__cvta_generic_to_shared(smem);

    const int tid = threadIdx.x;
    const int wid = tid >> 5, lane = tid & 31;
    const int gid = lane >> 2, t4 = lane & 3;
    const int wm = (wid >> 1) * 32;
    const int wn = (wid & 1) * 32;
    const int b  = blockIdx.z;
    // m on blockIdx.x (fastest): CTAs sharing one B tile are co-scheduled -> B L2 reuse
    const int m0 = blockIdx.x * BM;
    const int n0 = blockIdx.y * BN;
    const size_t brow0 = (size_t)b * HWD + n0;

    const int lrow = lane & 15;
    const int lka  = (lane & 16) ? 16 : 0;
    const uint32_t aoff = (wm + lrow) * PITCHB + lka;
    const uint32_t boff = (wn + lrow) * PITCHB + lka;

    float acc[2][4][4];
#pragma unroll
    for (int i = 0; i < 2; i++)
#pragma unroll
        for (int j = 0; j < 4; j++)
#pragma unroll
            for (int c = 0; c < 4; c++) acc[i][j][c] = 0.f;

    stage_chunk(sb32, Ahi, Alo, Bhi, Blo, tid, m0, brow0, K, 0);
    CP_COMMIT();

    const int nc = K / BK;
    for (int ci = 0; ci < nc; ci++) {
        const uint32_t cur = sb32 + (ci & 1) * STAGE;
        if (ci + 1 < nc) {
            stage_chunk(sb32 + ((ci + 1) & 1) * STAGE, Ahi, Alo, Bhi, Blo,
                        tid, m0, brow0, K, (ci + 1) * BK);
            CP_COMMIT();
            CP_WAIT1();
        } else {
            CP_WAIT0();
        }
        __syncthreads();

#pragma unroll
        for (int k16 = 0; k16 < BK / 16; k16++) {
            const uint32_t kb2 = k16 * 32;
            uint32_t ah[2][4], al[2][4], bh[4][2], bl[4][2];
#pragma unroll
            for (int mt = 0; mt < 2; mt++) {
                uint32_t ad = cur + aoff + mt * 16 * PITCHB + kb2;
                LDSM_X4(ah[mt][0], ah[mt][1], ah[mt][2], ah[mt][3], ad + S_AHI);
                LDSM_X4(al[mt][0], al[mt][1], al[mt][2], al[mt][3], ad + S_ALO);
            }
#pragma unroll
            for (int pr = 0; pr < 2; pr++) {
                uint32_t bd = cur + boff + pr * 16 * PITCHB + kb2;
                LDSM_X4(bh[2*pr][0], bh[2*pr+1][0], bh[2*pr][1], bh[2*pr+1][1], bd + S_BHI);
                LDSM_X4(bl[2*pr][0], bl[2*pr+1][0], bl[2*pr][1], bl[2*pr+1][1], bd + S_BLO);
            }
#pragma unroll
            for (int mt = 0; mt < 2; mt++)
#pragma unroll
                for (int nt = 0; nt < 4; nt++) {
                    float* d = acc[mt][nt];
                    MMA_BF16(d[0],d[1],d[2],d[3], ah[mt][0],ah[mt][1],ah[mt][2],ah[mt][3], bh[nt][0],bh[nt][1]);
                    MMA_BF16(d[0],d[1],d[2],d[3], ah[mt][0],ah[mt][1],ah[mt][2],ah[mt][3], bl[nt][0],bl[nt][1]);
                    MMA_BF16(d[0],d[1],d[2],d[3], al[mt][0],al[mt][1],al[mt][2],al[mt][3], bh[nt][0],bh[nt][1]);
                }
        }
        __syncthreads();
    }

#pragma unroll
    for (int mt = 0; mt < 2; mt++) {
        int m = m0 + wm + mt * 16 + gid;
#pragma unroll
        for (int nt = 0; nt < 4; nt++) {
            int n = n0 + wn + nt * 8 + 2 * t4;
            float* d = acc[mt][nt];
            float* y0 = Y + ((size_t)b * M + m) * HWD + n;
            float* y1 = Y + ((size_t)b * M + m + 8) * HWD + n;
            *(float2*)y0 = make_float2(d[0], d[1]);
            *(float2*)y1 = make_float2(d[2], d[3]);
        }
    }
}

// ---------------- Local windowed attention (unchanged winner) ----------------
__global__ __launch_bounds__(512, 1)
void attn_kernel(const float* __restrict__ qh, const float* __restrict__ kh,
                 const float* __restrict__ vh,
                 __nv_bfloat16* __restrict__ ohi, __nv_bfloat16* __restrict__ olo)
{
    extern __shared__ float4 sm4[];

    const int tid = threadIdx.x;
    const int bz = blockIdx.z;
    const int b = bz >> 3;
    const int h = bz & 7;
    const int x0 = blockIdx.x * ATW - RAD;
    const int y0 = blockIdx.y * ATH - RAD;
    const size_t hbase = ((size_t)b * CO + (size_t)h * DK) * HWD;

    {
        const float* kb = kh + hbase;
        for (int pos = tid; pos < ANPOS; pos += 512) {
            int hy = pos / AHLW;
            int hx = pos - hy * AHLW;
            int yy = y0 + hy, xx = x0 + hx;
            if ((unsigned)yy < HH && (unsigned)xx < WW) {
                const float* g = kb + (size_t)yy * WW + xx;
#pragma unroll
                for (int c4 = 0; c4 < NC4; c4++) {
                    float4 t;
                    t.x = g[(size_t)(c4*4+0) * HWD];
                    t.y = g[(size_t)(c4*4+1) * HWD];
                    t.z = g[(size_t)(c4*4+2) * HWD];
                    t.w = g[(size_t)(c4*4+3) * HWD];
                    sm4[c4 * ANPOS + pos] = t;
                }
            } else {
                float4 z = {0.f, 0.f, 0.f, 0.f};
#pragma unroll
                for (int c4 = 0; c4 < NC4; c4++) sm4[c4 * ANPOS + pos] = z;
            }
        }
    }
    __syncthreads();

    const int tx = tid & 31;
    const int ty = tid >> 5;
    const int gx = blockIdx.x * ATW + tx;
    const int gy = blockIdx.y * ATH + ty;
    const size_t pbase = hbase + (size_t)gy * WW + gx;
    const int sb = ty * AHLW + tx;

    float sc[NN];
#pragma unroll
    for (int d = 0; d < NN; d++) sc[d] = 0.f;

    for (int c4 = 0; c4 < NC4; c4++) {
        float q0 = qh[pbase + (size_t)(c4*4+0) * HWD];
        float q1 = qh[pbase + (size_t)(c4*4+1) * HWD];
        float q2 = qh[pbase + (size_t)(c4*4+2) * HWD];
        float q3 = qh[pbase + (size_t)(c4*4+3) * HWD];
        const float4* kc = sm4 + c4 * ANPOS + sb;
#pragma unroll
        for (int dy = 0; dy < KER; dy++) {
#pragma unroll
            for (int dx = 0; dx < KER; dx++) {
                float4 k4 = kc[dy * AHLW + dx];
                int d = dy * KER + dx;
                sc[d] = fmaf(q0, k4.x, fmaf(q1, k4.y, fmaf(q2, k4.z, fmaf(q3, k4.w, sc[d]))));
            }
        }
    }
    __syncthreads();

    {
        const float* vb = vh + hbase;
        for (int pos = tid; pos < ANPOS; pos += 512) {
            int hy = pos / AHLW;
            int hx = pos - hy * AHLW;
            int yy = y0 + hy, xx = x0 + hx;
            if ((unsigned)yy < HH && (unsigned)xx < WW) {
                const float* g = vb + (size_t)yy * WW + xx;
#pragma unroll
                for (int c4 = 0; c4 < NC4; c4++) {
                    float4 t;
                    t.x = g[(size_t)(c4*4+0) * HWD];
                    t.y = g[(size_t)(c4*4+1) * HWD];
                    t.z = g[(size_t)(c4*4+2) * HWD];
                    t.w = g[(size_t)(c4*4+3) * HWD];
                    sm4[c4 * ANPOS + pos] = t;
                }
            } else {
                float4 z = {0.f, 0.f, 0.f, 0.f};
#pragma unroll
                for (int c4 = 0; c4 < NC4; c4++) sm4[c4 * ANPOS + pos] = z;
            }
        }
    }

    {
        const float invT = 0.125f;
        float mx = sc[0];
#pragma unroll
        for (int d = 1; d < NN; d++) mx = fmaxf(mx, sc[d]);
        float ssum = 0.f;
#pragma unroll
        for (int d = 0; d < NN; d++) {
            float e = __expf((sc[d] - mx) * invT);
            sc[d] = e;
            ssum += e;
        }
        float rinv = 1.f / ssum;
#pragma unroll
        for (int d = 0; d < NN; d++) sc[d] *= rinv;
    }
    __syncthreads();

    const size_t obase = ((size_t)b * HWD + (size_t)gy * WW + gx) * CO + (size_t)h * DK;
    for (int c4 = 0; c4 < NC4; c4++) {
        const float4* vc = sm4 + c4 * ANPOS + sb;
        float a0 = 0.f, a1 = 0.f, a2 = 0.f, a3 = 0.f;
#pragma unroll
        for (int dy = 0; dy < KER; dy++) {
#pragma unroll
            for (int dx = 0; dx < KER; dx++) {
                float4 v4 = vc[dy * AHLW + dx];
                float w = sc[dy * KER + dx];
                a0 = fmaf(w, v4.x, a0);
                a1 = fmaf(w, v4.y, a1);
                a2 = fmaf(w, v4.z, a2);
                a3 = fmaf(w, v4.w, a3);
            }
        }
        __nv_bfloat16 h0 = __float2bfloat16(a0), h1 = __float2bfloat16(a1);
        __nv_bfloat16 h2 = __float2bfloat16(a2), h3 = __float2bfloat16(a3);
        *(__nv_bfloat162*)(ohi + obase + c4*4)     = __halves2bfloat162(h0, h1);
        *(__nv_bfloat162*)(ohi + obase + c4*4 + 2) = __halves2bfloat162(h2, h3);
        *(__nv_bfloat162*)(olo + obase + c4*4)     = __halves2bfloat162(
            __float2bfloat16(a0 - __bfloat162float(h0)),
            __float2bfloat16(a1 - __bfloat162float(h1)));
        *(__nv_bfloat162*)(olo + obase + c4*4 + 2) = __halves2bfloat162(
            __float2bfloat16(a2 - __bfloat162float(h2)),
            __float2bfloat16(a3 - __bfloat162float(h3)));
    }
}

// ---------------- residual + LayerNorm2d ----------------
__global__ __launch_bounds__(256)
void ln_kernel(const float* __restrict__ fc, const float* __restrict__ res,
               const float* __restrict__ lnw, const float* __restrict__ lnb,
               float* __restrict__ out)
{
    int p = blockIdx.x * 256 + threadIdx.x;
    int b = p / HWD;
    int pp = p - b * HWD;
    const float* f = fc + (size_t)b * CC * HWD + pp;
    const float* r = res + (size_t)b * CC * HWD + pp;

    float s = 0.f, s2 = 0.f;
#pragma unroll 4
    for (int c = 0; c < CC; c++) {
        float v = f[(size_t)c * HWD] + r[(size_t)c * HWD];
        s += v;
        s2 = fmaf(v, v, s2);
    }
    float mu = s * (1.f / CC);
    float var = s2 * (1.f / CC) - mu * mu;
    float inv = rsqrtf(var + LN_EPS);

    float* o = out + (size_t)b * CC * HWD + pp;
#pragma unroll 4
    for (int c = 0; c < CC; c++) {
        float v = f[(size_t)c * HWD] + r[(size_t)c * HWD];
        o[(size_t)c * HWD] = lnw[c] * ((v - mu) * inv) + lnb[c];
    }
}

// ---------------- launch ----------------
extern "C" void kernel_launch(void* const* d_in, const int* in_sizes, int n_in,
                              void* d_out, int out_size)
{
    const float* q   = (const float*)d_in[0];
    const float* k   = (const float*)d_in[1];
    const float* v   = (const float*)d_in[2];
    const float* Wq  = (const float*)d_in[3];
    const float* Wk  = (const float*)d_in[4];
    const float* Wv  = (const float*)d_in[5];
    const float* Wfc = (const float*)d_in[6];
    const float* lnw = (const float*)d_in[7];
    const float* lnb = (const float*)d_in[8];

    float *qh, *kh, *vh;
    __nv_bfloat16 *xhi, *xlo, *atthi, *attlo, *whi, *wlo;
    cudaGetSymbolAddress((void**)&qh, g_qh);
    cudaGetSymbolAddress((void**)&kh, g_kh);
    cudaGetSymbolAddress((void**)&vh, g_vh);
    cudaGetSymbolAddress((void**)&xhi, g_xhi);
    cudaGetSymbolAddress((void**)&xlo, g_xlo);
    cudaGetSymbolAddress((void**)&atthi, g_atthi);
    cudaGetSymbolAddress((void**)&attlo, g_attlo);
    cudaGetSymbolAddress((void**)&whi, g_whi);
    cudaGetSymbolAddress((void**)&wlo, g_wlo);
    float* fcb = qh;

    const size_t NX = (size_t)BB * CC * HWD;
    const int NW = CO * CC;

    dim3 tg(HWD / 32, CC / 32, BB);
    tsplit_kernel<<<tg, 256>>>(q, xhi + 0*NX, xlo + 0*NX);
    tsplit_kernel<<<tg, 256>>>(k, xhi + 1*NX, xlo + 1*NX);
    tsplit_kernel<<<tg, 256>>>(v, xhi + 2*NX, xlo + 2*NX);
    split_kernel<<<NW / 1024, 256>>>(Wq,  whi + 0*NW, wlo + 0*NW, NW);
    split_kernel<<<NW / 1024, 256>>>(Wk,  whi + 1*NW, wlo + 1*NW, NW);
    split_kernel<<<NW / 1024, 256>>>(Wv,  whi + 2*NW, wlo + 2*NW, NW);
    split_kernel<<<NW / 1024, 256>>>(Wfc, whi + 3*NW, wlo + 3*NW, NW);

    cudaFuncSetAttribute(mma_gemm, cudaFuncAttributeMaxDynamicSharedMemorySize, GEMM_SMEM);

    // grid: x = m-blocks (fastest) so CTAs sharing a B tile run concurrently
    dim3 gp(CO / BM, HWD / BN, BB);
    mma_gemm<<<gp, 256, GEMM_SMEM>>>(whi + 0*NW, wlo + 0*NW, xhi + 0*NX, xlo + 0*NX, qh, CO, CC);
    mma_gemm<<<gp, 256, GEMM_SMEM>>>(whi + 1*NW, wlo + 1*NW, xhi + 1*NX, xlo + 1*NX, kh, CO, CC);
    mma_gemm<<<gp, 256, GEMM_SMEM>>>(whi + 2*NW, wlo + 2*NW, xhi + 2*NX, xlo + 2*NX, vh, CO, CC);

    int smem = NC4 * ANPOS * (int)sizeof(float4);
    cudaFuncSetAttribute(attn_kernel, cudaFuncAttributeMaxDynamicSharedMemorySize, smem);
    dim3 ga(WW / ATW, HH / ATH, BB * NHEAD);
    attn_kernel<<<ga, 512, smem>>>(qh, kh, vh, atthi, attlo);

    dim3 gf(CC / BM, HWD / BN, BB);
    mma_gemm<<<gf, 256, GEMM_SMEM>>>(whi + 3*NW, wlo + 3*NW, atthi, attlo, fcb, CC, CO);

    ln_kernel<<<(BB * HWD) / 256, 256>>>(fcb, q, lnw, lnb, (float*)d_out);
}